// round 2
// baseline (speedup 1.0000x reference)
#include <cuda_runtime.h>
#include <cstdint>

#define T_TOK      4096
#define D_MODEL    1024
#define D_FF       4096
#define NUM_EXP    8
#define TOPK       2

// ---------------- scratch (static __device__, no allocations) ----------------
__device__ int   g_cnt[NUM_EXP];
__device__ int   g_idx[NUM_EXP][T_TOK];     // token index per expert slot
__device__ float g_wt [NUM_EXP][T_TOK];     // renormalized gate weight per slot
__device__ float g_h  [(size_t)NUM_EXP * T_TOK * D_FF];   // 512 MB fp32 h buffer

// ---------------- kernel 0: zero counters ----------------
__global__ void k_zero_cnt() {
    if (threadIdx.x < NUM_EXP) g_cnt[threadIdx.x] = 0;
}

// ---------------- kernel 0b: zero output ----------------
__global__ void k_zero_out(float* out, int n) {
    int i = blockIdx.x * blockDim.x + threadIdx.x;
    if (i < n) out[i] = 0.0f;
}

// ---------------- kernel 1: router (warp per token) ----------------
__global__ void k_router(const float* __restrict__ x,
                         const float* __restrict__ Wg) {
    int warp = (blockIdx.x * blockDim.x + threadIdx.x) >> 5;
    int lane = threadIdx.x & 31;
    if (warp >= T_TOK) return;
    const float* xr = x + (size_t)warp * D_MODEL;

    float acc[NUM_EXP];
#pragma unroll
    for (int e = 0; e < NUM_EXP; e++) acc[e] = 0.0f;

    for (int k = lane; k < D_MODEL; k += 32) {
        float xv = xr[k];
        const float4* wg4 = (const float4*)(Wg + (size_t)k * NUM_EXP);
        float4 w0 = wg4[0], w1 = wg4[1];
        acc[0] += xv * w0.x; acc[1] += xv * w0.y;
        acc[2] += xv * w0.z; acc[3] += xv * w0.w;
        acc[4] += xv * w1.x; acc[5] += xv * w1.y;
        acc[6] += xv * w1.z; acc[7] += xv * w1.w;
    }
#pragma unroll
    for (int e = 0; e < NUM_EXP; e++)
#pragma unroll
        for (int off = 16; off > 0; off >>= 1)
            acc[e] += __shfl_xor_sync(0xffffffffu, acc[e], off);

    if (lane == 0) {
        float m = acc[0];
#pragma unroll
        for (int e = 1; e < NUM_EXP; e++) m = fmaxf(m, acc[e]);
        float p[NUM_EXP]; float s = 0.0f;
#pragma unroll
        for (int e = 0; e < NUM_EXP; e++) { p[e] = __expf(acc[e] - m); s += p[e]; }
        float inv = 1.0f / s;
#pragma unroll
        for (int e = 0; e < NUM_EXP; e++) p[e] *= inv;

        // top-2 (first index wins ties, matching jax top_k)
        int i1 = 0;
#pragma unroll
        for (int e = 1; e < NUM_EXP; e++) if (p[e] > p[i1]) i1 = e;
        int i2 = (i1 == 0) ? 1 : 0;
#pragma unroll
        for (int e = 0; e < NUM_EXP; e++)
            if (e != i1 && e != i2 && p[e] > p[i2]) i2 = e;

        float denom = 1.0f / (p[i1] + p[i2]);
        float w1v = p[i1] * denom;
        float w2v = p[i2] * denom;

        int s1 = atomicAdd(&g_cnt[i1], 1);
        g_idx[i1][s1] = warp; g_wt[i1][s1] = w1v;
        int s2 = atomicAdd(&g_cnt[i2], 1);
        g_idx[i2][s2] = warp; g_wt[i2][s2] = w2v;
    }
}

// ---------------- tiled fp32 GEMM constants ----------------
#define BM 128
#define BN 128
#define BK 8
#define PAD 4   // shared padding (keeps 16B alignment: 132 % 4 == 0)

// ---------------- kernel 2: h = relu(gather(x) @ W1[e] + b1[e]) ----------------
__global__ __launch_bounds__(256, 2)
void k_gemm1(const float* __restrict__ x,
             const float* __restrict__ W1,
             const float* __restrict__ b1) {
    int e   = blockIdx.z;
    int cnt = g_cnt[e];
    int m0  = blockIdx.y * BM;
    if (m0 >= cnt) return;
    int n0  = blockIdx.x * BN;

    const float* W = W1 + (size_t)e * D_MODEL * D_FF;

    __shared__ float As[BK][BM + PAD];
    __shared__ float Bs[BK][BN + PAD];

    int tid  = threadIdx.x;
    // A load: 128 rows x 8 k, one float4 per thread
    int arow = tid >> 1;
    int akk  = (tid & 1) * 4;
    int grow = m0 + arow;
    bool avalid = (grow < cnt);
    int tok  = g_idx[e][avalid ? grow : 0];
    const float* aptr = x + (size_t)tok * D_MODEL + akk;
    // B load: 8 rows x 128 cols, one float4 per thread
    int brow = tid >> 5;
    int bcol = (tid & 31) * 4;
    const float* bptr = W + (size_t)brow * D_FF + n0 + bcol;

    int ty = tid >> 4, tx = tid & 15;
    float c[8][8];
#pragma unroll
    for (int i = 0; i < 8; i++)
#pragma unroll
        for (int j = 0; j < 8; j++) c[i][j] = 0.0f;

    for (int k0 = 0; k0 < D_MODEL; k0 += BK) {
        float4 av = avalid ? *(const float4*)(aptr + k0)
                           : make_float4(0.f, 0.f, 0.f, 0.f);
        As[akk + 0][arow] = av.x; As[akk + 1][arow] = av.y;
        As[akk + 2][arow] = av.z; As[akk + 3][arow] = av.w;
        *(float4*)&Bs[brow][bcol] = *(const float4*)(bptr + (size_t)k0 * D_FF);
        __syncthreads();
#pragma unroll
        for (int kk = 0; kk < BK; kk++) {
            float a[8], b[8];
            *(float4*)(a)     = *(float4*)&As[kk][ty * 4];
            *(float4*)(a + 4) = *(float4*)&As[kk][64 + ty * 4];
            *(float4*)(b)     = *(float4*)&Bs[kk][tx * 4];
            *(float4*)(b + 4) = *(float4*)&Bs[kk][64 + tx * 4];
#pragma unroll
            for (int i = 0; i < 8; i++)
#pragma unroll
                for (int j = 0; j < 8; j++) c[i][j] += a[i] * b[j];
        }
        __syncthreads();
    }

    // epilogue: relu(c + b1), write to g_h[e]
    const float* b1e = b1 + (size_t)e * D_FF;
#pragma unroll
    for (int i = 0; i < 8; i++) {
        int r = m0 + ((i < 4) ? (ty * 4 + i) : (64 + ty * 4 + i - 4));
        if (r >= cnt) continue;
        float* hrow = g_h + ((size_t)e * T_TOK + r) * D_FF;
#pragma unroll
        for (int j = 0; j < 8; j++) {
            int col = n0 + ((j < 4) ? (tx * 4 + j) : (64 + tx * 4 + j - 4));
            hrow[col] = fmaxf(c[i][j] + b1e[col], 0.0f);
        }
    }
}

// ---------------- kernel 3: out += (h @ W2[e] + b2[e]) * w  (atomic) ----------------
__global__ __launch_bounds__(256, 2)
void k_gemm2(const float* __restrict__ W2,
             const float* __restrict__ b2,
             float* __restrict__ out) {
    int e   = blockIdx.z;
    int cnt = g_cnt[e];
    int m0  = blockIdx.y * BM;
    if (m0 >= cnt) return;
    int n0  = blockIdx.x * BN;

    const float* W = W2 + (size_t)e * D_FF * D_MODEL;
    const float* A = g_h + (size_t)e * T_TOK * D_FF;

    __shared__ float As[BK][BM + PAD];
    __shared__ float Bs[BK][BN + PAD];

    int tid  = threadIdx.x;
    int arow = tid >> 1;
    int akk  = (tid & 1) * 4;
    int grow = m0 + arow;
    bool avalid = (grow < cnt);
    const float* aptr = A + (size_t)(avalid ? grow : 0) * D_FF + akk;
    int brow = tid >> 5;
    int bcol = (tid & 31) * 4;
    const float* bptr = W + (size_t)brow * D_MODEL + n0 + bcol;

    int ty = tid >> 4, tx = tid & 15;
    float c[8][8];
#pragma unroll
    for (int i = 0; i < 8; i++)
#pragma unroll
        for (int j = 0; j < 8; j++) c[i][j] = 0.0f;

    for (int k0 = 0; k0 < D_FF; k0 += BK) {
        float4 av = avalid ? *(const float4*)(aptr + k0)
                           : make_float4(0.f, 0.f, 0.f, 0.f);
        As[akk + 0][arow] = av.x; As[akk + 1][arow] = av.y;
        As[akk + 2][arow] = av.z; As[akk + 3][arow] = av.w;
        *(float4*)&Bs[brow][bcol] = *(const float4*)(bptr + (size_t)k0 * D_MODEL);
        __syncthreads();
#pragma unroll
        for (int kk = 0; kk < BK; kk++) {
            float a[8], b[8];
            *(float4*)(a)     = *(float4*)&As[kk][ty * 4];
            *(float4*)(a + 4) = *(float4*)&As[kk][64 + ty * 4];
            *(float4*)(b)     = *(float4*)&Bs[kk][tx * 4];
            *(float4*)(b + 4) = *(float4*)&Bs[kk][64 + tx * 4];
#pragma unroll
            for (int i = 0; i < 8; i++)
#pragma unroll
                for (int j = 0; j < 8; j++) c[i][j] += a[i] * b[j];
        }
        __syncthreads();
    }

    const float* b2e = b2 + (size_t)e * D_MODEL;
#pragma unroll
    for (int i = 0; i < 8; i++) {
        int r = m0 + ((i < 4) ? (ty * 4 + i) : (64 + ty * 4 + i - 4));
        if (r >= cnt) continue;
        int   tok = g_idx[e][r];
        float w   = g_wt[e][r];
        float* orow = out + (size_t)tok * D_MODEL;
#pragma unroll
        for (int j = 0; j < 8; j++) {
            int col = n0 + ((j < 4) ? (tx * 4 + j) : (64 + tx * 4 + j - 4));
            atomicAdd(&orow[col], (c[i][j] + b2e[col]) * w);
        }
    }
}

// ---------------- launch ----------------
extern "C" void kernel_launch(void* const* d_in, const int* in_sizes, int n_in,
                              void* d_out, int out_size) {
    const float* x  = (const float*)d_in[0];
    const float* Wg = (const float*)d_in[1];
    const float* W1 = (const float*)d_in[2];
    const float* b1 = (const float*)d_in[3];
    const float* W2 = (const float*)d_in[4];
    const float* b2 = (const float*)d_in[5];
    float* out = (float*)d_out;

    k_zero_cnt<<<1, 32>>>();
    {
        int n = T_TOK * D_MODEL;
        k_zero_out<<<(n + 255) / 256, 256>>>(out, n);
    }
    // router: warp per token, 8 warps per block
    k_router<<<T_TOK / 8, 256>>>(x, Wg);

    dim3 g1(D_FF / BN, (T_TOK + BM - 1) / BM, NUM_EXP);
    k_gemm1<<<g1, 256>>>(x, W1, b1);

    dim3 g2(D_MODEL / BN, (T_TOK + BM - 1) / BM, NUM_EXP);
    k_gemm2<<<g2, 256>>>(W2, b2, out);
}

// round 4
// speedup vs baseline: 2.9267x; 2.9267x over previous
#include <cuda_runtime.h>
#include <cstdint>

#define T_TOK      4096
#define D_MODEL    1024
#define D_FF       4096
#define NUM_EXP    8

#define BM 128
#define BN 128
#define BK 32

// smem float-row pads (bank-conflict-free fragment loads)
#define APAD_ROW 36     // 32 + 4
#define BPAD_ROW 136    // 128 + 8
#define A_STAGE_BYTES (BM * APAD_ROW * 4)   // 18432
#define B_STAGE_BYTES (BK * BPAD_ROW * 4)   // 17408
#define OFF_A 0
#define OFF_B (2 * A_STAGE_BYTES)           // 36864
#define OFF_BIAS (OFF_B + 2 * B_STAGE_BYTES)        // 71680
#define SMEM_BYTES (OFF_BIAS + BN * 4)      // 72192

// ---------------- helpers ----------------
__device__ __forceinline__ uint32_t smem_to_u32(const void* p) {
    uint32_t a;
    asm("{ .reg .u64 t; cvta.to.shared.u64 t, %1; cvt.u32.u64 %0, t; }" : "=r"(a) : "l"(p));
    return a;
}
__device__ __forceinline__ float tf32r(float v) {
    uint32_t u;
    asm("cvt.rna.tf32.f32 %0, %1;" : "=r"(u) : "f"(v));
    return __uint_as_float(u);
}
__device__ __forceinline__ void cp_async16(uint32_t dst, const void* src) {
    asm volatile("cp.async.ca.shared.global [%0], [%1], 16;" :: "r"(dst), "l"(src));
}
__device__ __forceinline__ void cp_commit() { asm volatile("cp.async.commit_group;"); }
template<int N> __device__ __forceinline__ void cp_wait() {
    asm volatile("cp.async.wait_group %0;" :: "n"(N));
}
__device__ __forceinline__ void mma_tf32(float* d, const uint32_t* a, const uint32_t* b) {
    asm volatile(
        "mma.sync.aligned.m16n8k8.row.col.f32.tf32.tf32.f32 "
        "{%0,%1,%2,%3}, {%4,%5,%6,%7}, {%8,%9}, {%0,%1,%2,%3};"
        : "+f"(d[0]), "+f"(d[1]), "+f"(d[2]), "+f"(d[3])
        : "r"(a[0]), "r"(a[1]), "r"(a[2]), "r"(a[3]), "r"(b[0]), "r"(b[1]));
}

// ---------------- scratch ----------------
__device__ int   g_cnt[NUM_EXP];
__device__ int   g_base[NUM_EXP];
__device__ int   g_idx[NUM_EXP][T_TOK];
__device__ float g_wt [NUM_EXP][T_TOK];
__device__ float g_xg [(size_t)2 * T_TOK * D_MODEL];         // tf32-rounded gathered x
__device__ float g_h  [(size_t)2 * T_TOK * D_FF];            // tf32-rounded h
__device__ float g_w1c[(size_t)NUM_EXP * D_MODEL * D_FF];    // tf32-rounded W1
__device__ float g_w2c[(size_t)NUM_EXP * D_FF * D_MODEL];    // tf32-rounded W2

// ---------------- small kernels ----------------
__global__ void k_zero_cnt() { if (threadIdx.x < NUM_EXP) g_cnt[threadIdx.x] = 0; }

__global__ void k_zero_out(float4* out, int n4) {
    int i = blockIdx.x * blockDim.x + threadIdx.x;
    if (i < n4) out[i] = make_float4(0.f, 0.f, 0.f, 0.f);
}

__global__ void k_scan() {
    if (threadIdx.x == 0) {
        int s = 0;
        for (int e = 0; e < NUM_EXP; e++) { g_base[e] = s; s += g_cnt[e]; }
    }
}

__global__ void k_cvt(const float4* __restrict__ src, float4* __restrict__ dst, int n4) {
    int i = blockIdx.x * blockDim.x + threadIdx.x;
    if (i < n4) {
        float4 v = src[i];
        v.x = tf32r(v.x); v.y = tf32r(v.y); v.z = tf32r(v.z); v.w = tf32r(v.w);
        dst[i] = v;
    }
}

__global__ void k_router(const float* __restrict__ x, const float* __restrict__ Wg) {
    int warp = (blockIdx.x * blockDim.x + threadIdx.x) >> 5;
    int lane = threadIdx.x & 31;
    if (warp >= T_TOK) return;
    const float* xr = x + (size_t)warp * D_MODEL;
    float acc[NUM_EXP];
#pragma unroll
    for (int e = 0; e < NUM_EXP; e++) acc[e] = 0.f;
    for (int k = lane; k < D_MODEL; k += 32) {
        float xv = xr[k];
        const float4* wg4 = (const float4*)(Wg + (size_t)k * NUM_EXP);
        float4 w0 = wg4[0], w1 = wg4[1];
        acc[0] += xv * w0.x; acc[1] += xv * w0.y; acc[2] += xv * w0.z; acc[3] += xv * w0.w;
        acc[4] += xv * w1.x; acc[5] += xv * w1.y; acc[6] += xv * w1.z; acc[7] += xv * w1.w;
    }
#pragma unroll
    for (int e = 0; e < NUM_EXP; e++)
#pragma unroll
        for (int off = 16; off > 0; off >>= 1)
            acc[e] += __shfl_xor_sync(0xffffffffu, acc[e], off);
    if (lane == 0) {
        float m = acc[0];
#pragma unroll
        for (int e = 1; e < NUM_EXP; e++) m = fmaxf(m, acc[e]);
        float p[NUM_EXP]; float s = 0.f;
#pragma unroll
        for (int e = 0; e < NUM_EXP; e++) { p[e] = __expf(acc[e] - m); s += p[e]; }
        float inv = 1.f / s;
#pragma unroll
        for (int e = 0; e < NUM_EXP; e++) p[e] *= inv;
        int i1 = 0;
#pragma unroll
        for (int e = 1; e < NUM_EXP; e++) if (p[e] > p[i1]) i1 = e;
        int i2 = (i1 == 0) ? 1 : 0;
#pragma unroll
        for (int e = 0; e < NUM_EXP; e++) if (e != i1 && e != i2 && p[e] > p[i2]) i2 = e;
        float den = 1.f / (p[i1] + p[i2]);
        int s1 = atomicAdd(&g_cnt[i1], 1);
        g_idx[i1][s1] = warp; g_wt[i1][s1] = p[i1] * den;
        int s2 = atomicAdd(&g_cnt[i2], 1);
        g_idx[i2][s2] = warp; g_wt[i2][s2] = p[i2] * den;
    }
}

// gather + tf32 round
__global__ void k_gather(const float* __restrict__ x) {
    int e = blockIdx.y;
    int cnt = g_cnt[e];
    int b = g_base[e];
    for (int i = blockIdx.x; i < cnt; i += gridDim.x) {
        int tok = g_idx[e][i];
        const float4* s = (const float4*)(x + (size_t)tok * D_MODEL);
        float4* d = (float4*)(g_xg + (size_t)(b + i) * D_MODEL);
        float4 v = s[threadIdx.x];
        v.x = tf32r(v.x); v.y = tf32r(v.y); v.z = tf32r(v.z); v.w = tf32r(v.w);
        d[threadIdx.x] = v;
    }
}

// ---------------- tf32 mma.sync GEMM ----------------
// MODE 0: g_h[base+m][n] = tf32r( relu( g_xg @ W1c + b1 ) )   KTOT=1024 NTOT=4096
// MODE 1: out[tok][n] += ( g_h @ W2c + b2 ) * wgt             KTOT=4096 NTOT=1024
template<int KTOT, int NTOT, int MODE>
__global__ __launch_bounds__(256)
void k_mma_gemm(const float* __restrict__ Bconv, const float* __restrict__ bias,
                float* __restrict__ outp) {
    int e   = blockIdx.z;
    int cnt = g_cnt[e];
    int m0  = blockIdx.y * BM;
    if (m0 >= cnt) return;
    int n0  = blockIdx.x * BN;
    int base = g_base[e];

    extern __shared__ char smem[];
    uint32_t su = smem_to_u32(smem);
    int tid = threadIdx.x, wid = tid >> 5, lane = tid & 31;

    float* bias_s = (float*)(smem + OFF_BIAS);
    if (tid < BN) bias_s[tid] = bias[(size_t)e * NTOT + n0 + tid];

    const float* Abase = MODE ? g_h : g_xg;
    const float* Bexp  = Bconv + (size_t)e * (size_t)KTOT * NTOT + n0;
    int lastrow = base + cnt - 1;

    // ---- per-thread cp.async coordinates ----
    // A: 128 rows x 8 float4 per row => 1024 f4, 4 per thread
    const float* a_src[4]; uint32_t a_dst[4];
#pragma unroll
    for (int p = 0; p < 4; p++) {
        int idx = p * 256 + tid;
        int row = idx >> 3, c4 = idx & 7;
        int gr = base + m0 + row; if (gr > lastrow) gr = lastrow;
        a_src[p] = Abase + (size_t)gr * KTOT + c4 * 4;
        a_dst[p] = su + OFF_A + (uint32_t)(row * APAD_ROW + c4 * 4) * 4;
    }
    // B: 32 k-rows x 32 float4 per row => 1024 f4, 4 per thread
    const float* b_src[4]; uint32_t b_dst[4];
#pragma unroll
    for (int p = 0; p < 4; p++) {
        int idx = p * 256 + tid;
        int row = idx >> 5, c4 = idx & 31;
        b_src[p] = Bexp + (size_t)row * NTOT + c4 * 4;
        b_dst[p] = su + OFF_B + (uint32_t)(row * BPAD_ROW + c4 * 4) * 4;
    }

    constexpr int NCH = KTOT / BK;

    // prologue: chunk 0 -> stage 0
#pragma unroll
    for (int p = 0; p < 4; p++) cp_async16(a_dst[p], a_src[p]);
#pragma unroll
    for (int p = 0; p < 4; p++) cp_async16(b_dst[p], b_src[p]);
    cp_commit();

    int wm = wid & 1, wn = wid >> 1;      // warp tile: 64x32
    float acc[4][4][4];
#pragma unroll
    for (int i = 0; i < 4; i++)
#pragma unroll
        for (int j = 0; j < 4; j++)
#pragma unroll
            for (int r = 0; r < 4; r++) acc[i][j][r] = 0.f;

    int g = lane >> 2, tg = lane & 3;

    for (int c = 0; c < NCH; c++) {
        int s = c & 1;
        if (c + 1 < NCH) {
            int s2 = s ^ 1;
            uint32_t ash = (uint32_t)(s2 * A_STAGE_BYTES);
            uint32_t bsh = (uint32_t)(s2 * B_STAGE_BYTES);
#pragma unroll
            for (int p = 0; p < 4; p++) cp_async16(a_dst[p] + ash, a_src[p] + (c + 1) * BK);
#pragma unroll
            for (int p = 0; p < 4; p++) cp_async16(b_dst[p] + bsh, b_src[p] + (size_t)(c + 1) * BK * NTOT);
            cp_commit();
            cp_wait<1>();
        } else {
            cp_wait<0>();
        }
        __syncthreads();

        const uint32_t* As = (const uint32_t*)(smem + OFF_A + s * A_STAGE_BYTES);
        const uint32_t* Bs = (const uint32_t*)(smem + OFF_B + s * B_STAGE_BYTES);
#pragma unroll
        for (int kk = 0; kk < 4; kk++) {
            int k = kk * 8;
            uint32_t af[4][4], bf[4][2];
#pragma unroll
            for (int mt = 0; mt < 4; mt++) {
                int r0 = wm * 64 + mt * 16 + g;
                af[mt][0] = As[r0 * APAD_ROW + k + tg];
                af[mt][1] = As[(r0 + 8) * APAD_ROW + k + tg];
                af[mt][2] = As[r0 * APAD_ROW + k + tg + 4];
                af[mt][3] = As[(r0 + 8) * APAD_ROW + k + tg + 4];
            }
#pragma unroll
            for (int nt = 0; nt < 4; nt++) {
                int col = wn * 32 + nt * 8 + g;
                bf[nt][0] = Bs[(k + tg) * BPAD_ROW + col];
                bf[nt][1] = Bs[(k + tg + 4) * BPAD_ROW + col];
            }
#pragma unroll
            for (int mt = 0; mt < 4; mt++)
#pragma unroll
                for (int nt = 0; nt < 4; nt++)
                    mma_tf32(acc[mt][nt], af[mt], bf[nt]);
        }
        __syncthreads();
    }

    // ---- epilogue ----
    int nbase = wn * 32 + tg * 2;
#pragma unroll
    for (int mt = 0; mt < 4; mt++) {
        int m_lo = m0 + wm * 64 + mt * 16 + g;
        int m_hi = m_lo + 8;
        bool v_lo = (m_lo < cnt), v_hi = (m_hi < cnt);
        if (MODE == 0) {
            float* row_lo = outp + (size_t)(base + (v_lo ? m_lo : 0)) * D_FF + n0;
            float* row_hi = outp + (size_t)(base + (v_hi ? m_hi : 0)) * D_FF + n0;
#pragma unroll
            for (int nt = 0; nt < 4; nt++) {
                int col = nbase + nt * 8;
                if (v_lo) {
                    row_lo[col]     = tf32r(fmaxf(acc[mt][nt][0] + bias_s[col], 0.f));
                    row_lo[col + 1] = tf32r(fmaxf(acc[mt][nt][1] + bias_s[col + 1], 0.f));
                }
                if (v_hi) {
                    row_hi[col]     = tf32r(fmaxf(acc[mt][nt][2] + bias_s[col], 0.f));
                    row_hi[col + 1] = tf32r(fmaxf(acc[mt][nt][3] + bias_s[col + 1], 0.f));
                }
            }
        } else {
            int tok_lo = 0, tok_hi = 0; float w_lo = 0.f, w_hi = 0.f;
            if (v_lo) { tok_lo = g_idx[e][m_lo]; w_lo = g_wt[e][m_lo]; }
            if (v_hi) { tok_hi = g_idx[e][m_hi]; w_hi = g_wt[e][m_hi]; }
            float* row_lo = outp + (size_t)tok_lo * D_MODEL + n0;
            float* row_hi = outp + (size_t)tok_hi * D_MODEL + n0;
#pragma unroll
            for (int nt = 0; nt < 4; nt++) {
                int col = nbase + nt * 8;
                if (v_lo) {
                    atomicAdd(row_lo + col,     (acc[mt][nt][0] + bias_s[col]) * w_lo);
                    atomicAdd(row_lo + col + 1, (acc[mt][nt][1] + bias_s[col + 1]) * w_lo);
                }
                if (v_hi) {
                    atomicAdd(row_hi + col,     (acc[mt][nt][2] + bias_s[col]) * w_hi);
                    atomicAdd(row_hi + col + 1, (acc[mt][nt][3] + bias_s[col + 1]) * w_hi);
                }
            }
        }
    }
}

// ---------------- launch ----------------
extern "C" void kernel_launch(void* const* d_in, const int* in_sizes, int n_in,
                              void* d_out, int out_size) {
    const float* x  = (const float*)d_in[0];
    const float* Wg = (const float*)d_in[1];
    const float* W1 = (const float*)d_in[2];
    const float* b1 = (const float*)d_in[3];
    const float* W2 = (const float*)d_in[4];
    const float* b2 = (const float*)d_in[5];
    float* out = (float*)d_out;

    static bool attr_done = false;
    if (!attr_done) {
        cudaFuncSetAttribute(k_mma_gemm<D_MODEL, D_FF, 0>,
                             cudaFuncAttributeMaxDynamicSharedMemorySize, SMEM_BYTES);
        cudaFuncSetAttribute(k_mma_gemm<D_FF, D_MODEL, 1>,
                             cudaFuncAttributeMaxDynamicSharedMemorySize, SMEM_BYTES);
        attr_done = true;
    }

    k_zero_cnt<<<1, 32>>>();
    {
        int n4 = T_TOK * D_MODEL / 4;
        k_zero_out<<<(n4 + 255) / 256, 256>>>((float4*)out, n4);
    }
    k_router<<<T_TOK / 8, 256>>>(x, Wg);
    k_scan<<<1, 32>>>();
    k_gather<<<dim3(512, NUM_EXP), 256>>>(x);

    {
        int n4 = NUM_EXP * D_MODEL * D_FF / 4;
        int blocks = (n4 + 255) / 256;
        float* w1c; cudaGetSymbolAddress((void**)&w1c, g_w1c);
        float* w2c; cudaGetSymbolAddress((void**)&w2c, g_w2c);
        k_cvt<<<blocks, 256>>>((const float4*)W1, (float4*)w1c, n4);
        k_cvt<<<blocks, 256>>>((const float4*)W2, (float4*)w2c, n4);
        float* hptr; cudaGetSymbolAddress((void**)&hptr, g_h);

        // GEMM1: h = relu(xg @ W1 + b1)
        k_mma_gemm<D_MODEL, D_FF, 0>
            <<<dim3(D_FF / BN, T_TOK / BM, NUM_EXP), 256, SMEM_BYTES>>>(w1c, b1, hptr);
        // GEMM2: out += (h @ W2 + b2) * w
        k_mma_gemm<D_FF, D_MODEL, 1>
            <<<dim3(D_MODEL / BN, T_TOK / BM, NUM_EXP), 256, SMEM_BYTES>>>(w2c, b2, out);
    }
}

// round 5
// speedup vs baseline: 5.4306x; 1.8555x over previous
#include <cuda_runtime.h>
#include <cuda_fp16.h>
#include <cstdint>

#define T_TOK   4096
#define D_MODEL 1024
#define D_FF    4096
#define NUM_EXP 8

#define BM 128
#define BN 256
#define BK 32
#define STAGES 4

// smem layout (bytes)
#define A_ROW_B 80        // 32 halves padded to 40 halves (80B): conflict-free LDSM
#define B_ROW_B 528       // 256 halves padded to 264 halves (528B)
#define A_STAGE (BM * A_ROW_B)              // 10240
#define B_STAGE (BK * B_ROW_B)              // 16896
#define OFF_A   0
#define OFF_B   (STAGES * A_STAGE)          // 40960
#define OFF_BIAS (OFF_B + STAGES * B_STAGE) // 108544
#define SMEM_BYTES (OFF_BIAS + BN * 4)      // 109568

// ---------------- helpers ----------------
__device__ __forceinline__ uint32_t smem_to_u32(const void* p) {
    uint32_t a;
    asm("{ .reg .u64 t; cvta.to.shared.u64 t, %1; cvt.u32.u64 %0, t; }" : "=r"(a) : "l"(p));
    return a;
}
__device__ __forceinline__ void cp_async16(uint32_t dst, const void* src) {
    asm volatile("cp.async.ca.shared.global [%0], [%1], 16;" :: "r"(dst), "l"(src));
}
__device__ __forceinline__ void cp_commit() { asm volatile("cp.async.commit_group;"); }
template<int N> __device__ __forceinline__ void cp_wait() {
    asm volatile("cp.async.wait_group %0;" :: "n"(N));
}
#define LDM_X4(r0, r1, r2, r3, addr) \
    asm volatile("ldmatrix.sync.aligned.m8n8.x4.shared.b16 {%0,%1,%2,%3}, [%4];" \
        : "=r"(r0), "=r"(r1), "=r"(r2), "=r"(r3) : "r"(addr))
#define LDM_X4_T(r0, r1, r2, r3, addr) \
    asm volatile("ldmatrix.sync.aligned.m8n8.x4.trans.shared.b16 {%0,%1,%2,%3}, [%4];" \
        : "=r"(r0), "=r"(r1), "=r"(r2), "=r"(r3) : "r"(addr))
#define MMA_F16(d, a, b) \
    asm volatile("mma.sync.aligned.m16n8k16.row.col.f32.f16.f16.f32 " \
        "{%0,%1,%2,%3},{%4,%5,%6,%7},{%8,%9},{%0,%1,%2,%3};" \
        : "+f"((d)[0]), "+f"((d)[1]), "+f"((d)[2]), "+f"((d)[3]) \
        : "r"((a)[0]), "r"((a)[1]), "r"((a)[2]), "r"((a)[3]), "r"((b)[0]), "r"((b)[1]))

// ---------------- scratch ----------------
__device__ int      g_cnt[NUM_EXP];
__device__ int      g_base[NUM_EXP];
__device__ int      g_idx[NUM_EXP][T_TOK];
__device__ uint32_t g_tk[2 * T_TOK];     // per-token packed (e<<12 | slot), [0]=top1
__device__ float    g_tw[2 * T_TOK];     // per-token renormalized weights
__device__ __half   g_xg [(size_t)2 * T_TOK * D_MODEL];    // gathered x, fp16
__device__ __half   g_h  [(size_t)2 * T_TOK * D_FF];       // hidden, fp16
__device__ float    g_y  [(size_t)2 * T_TOK * D_MODEL];    // per-assignment output
__device__ __half   g_w1h[(size_t)NUM_EXP * D_MODEL * D_FF];
__device__ __half   g_w2h[(size_t)NUM_EXP * D_FF * D_MODEL];

// ---------------- small kernels ----------------
__global__ void k_zero_cnt() { if (threadIdx.x < NUM_EXP) g_cnt[threadIdx.x] = 0; }

__global__ void k_scan() {
    if (threadIdx.x == 0) {
        int s = 0;
        for (int e = 0; e < NUM_EXP; e++) { g_base[e] = s; s += g_cnt[e]; }
    }
}

// fp32 -> fp16 (RN), 4 elems/thread
__global__ void k_cvt(const float4* __restrict__ src, __half* __restrict__ dst, int n4) {
    int i = blockIdx.x * blockDim.x + threadIdx.x;
    if (i < n4) {
        float4 v = src[i];
        __half2 h0 = __floats2half2_rn(v.x, v.y);
        __half2 h1 = __floats2half2_rn(v.z, v.w);
        uint2 u;
        u.x = *reinterpret_cast<uint32_t*>(&h0);
        u.y = *reinterpret_cast<uint32_t*>(&h1);
        *reinterpret_cast<uint2*>(dst + (size_t)i * 4) = u;
    }
}

__global__ void k_router(const float* __restrict__ x, const float* __restrict__ Wg) {
    int warp = (blockIdx.x * blockDim.x + threadIdx.x) >> 5;
    int lane = threadIdx.x & 31;
    if (warp >= T_TOK) return;
    const float* xr = x + (size_t)warp * D_MODEL;
    float acc[NUM_EXP];
#pragma unroll
    for (int e = 0; e < NUM_EXP; e++) acc[e] = 0.f;
    for (int k = lane; k < D_MODEL; k += 32) {
        float xv = xr[k];
        const float4* wg4 = (const float4*)(Wg + (size_t)k * NUM_EXP);
        float4 w0 = wg4[0], w1 = wg4[1];
        acc[0] += xv * w0.x; acc[1] += xv * w0.y; acc[2] += xv * w0.z; acc[3] += xv * w0.w;
        acc[4] += xv * w1.x; acc[5] += xv * w1.y; acc[6] += xv * w1.z; acc[7] += xv * w1.w;
    }
#pragma unroll
    for (int e = 0; e < NUM_EXP; e++)
#pragma unroll
        for (int off = 16; off > 0; off >>= 1)
            acc[e] += __shfl_xor_sync(0xffffffffu, acc[e], off);
    if (lane == 0) {
        float m = acc[0];
#pragma unroll
        for (int e = 1; e < NUM_EXP; e++) m = fmaxf(m, acc[e]);
        float p[NUM_EXP]; float s = 0.f;
#pragma unroll
        for (int e = 0; e < NUM_EXP; e++) { p[e] = __expf(acc[e] - m); s += p[e]; }
        float inv = 1.f / s;
#pragma unroll
        for (int e = 0; e < NUM_EXP; e++) p[e] *= inv;
        int i1 = 0;
#pragma unroll
        for (int e = 1; e < NUM_EXP; e++) if (p[e] > p[i1]) i1 = e;
        int i2 = (i1 == 0) ? 1 : 0;
#pragma unroll
        for (int e = 0; e < NUM_EXP; e++) if (e != i1 && e != i2 && p[e] > p[i2]) i2 = e;
        float den = 1.f / (p[i1] + p[i2]);
        int s1 = atomicAdd(&g_cnt[i1], 1);
        g_idx[i1][s1] = warp;
        int s2 = atomicAdd(&g_cnt[i2], 1);
        g_idx[i2][s2] = warp;
        g_tk[warp * 2]     = ((uint32_t)i1 << 12) | (uint32_t)s1;
        g_tk[warp * 2 + 1] = ((uint32_t)i2 << 12) | (uint32_t)s2;
        g_tw[warp * 2]     = p[i1] * den;
        g_tw[warp * 2 + 1] = p[i2] * den;
    }
}

// gather x rows -> compacted fp16
__global__ void k_gather(const float* __restrict__ x) {
    int e = blockIdx.y;
    int cnt = g_cnt[e];
    int b = g_base[e];
    for (int i = blockIdx.x; i < cnt; i += gridDim.x) {
        int tok = g_idx[e][i];
        float4 v = ((const float4*)(x + (size_t)tok * D_MODEL))[threadIdx.x];
        __half2 h0 = __floats2half2_rn(v.x, v.y);
        __half2 h1 = __floats2half2_rn(v.z, v.w);
        uint2 u;
        u.x = *reinterpret_cast<uint32_t*>(&h0);
        u.y = *reinterpret_cast<uint32_t*>(&h1);
        ((uint2*)(g_xg + (size_t)(b + i) * D_MODEL))[threadIdx.x] = u;
    }
}

// ---------------- fp16 mma GEMM ----------------
// MODE 0: g_h[base+m][n] = fp16(relu(xg @ W1h + b1))   KTOT=1024, NTOT=4096
// MODE 1: g_y[base+m][n] = fp32(h @ W2h)               KTOT=4096, NTOT=1024
template<int KTOT, int NTOT, int MODE>
__global__ __launch_bounds__(256)
void k_mma_gemm(const float* __restrict__ bias) {
    int e   = blockIdx.z;
    int cnt = g_cnt[e];
    int m0  = blockIdx.y * BM;
    if (m0 >= cnt) return;
    int n0  = blockIdx.x * BN;
    int base = g_base[e];

    extern __shared__ char smem[];
    uint32_t su = smem_to_u32(smem);
    int tid = threadIdx.x, wid = tid >> 5, lane = tid & 31;

    float* bias_s = (float*)(smem + OFF_BIAS);
    if (MODE == 0 && tid < BN) bias_s[tid] = bias[(size_t)e * NTOT + n0 + tid];

    const __half* Abase = MODE ? g_h : g_xg;
    const __half* Bexp  = (MODE ? g_w2h : g_w1h) + (size_t)e * KTOT * NTOT + n0;
    int lastrow = base + cnt - 1;

    // cp.async coordinates
    const __half* a_src[2]; uint32_t a_dst[2];
#pragma unroll
    for (int p = 0; p < 2; p++) {
        int idx = p * 256 + tid;
        int row = idx >> 2, c = idx & 3;   // 4x16B per 128-row A tile row
        int gr = base + m0 + row; if (gr > lastrow) gr = lastrow;
        a_src[p] = Abase + (size_t)gr * KTOT + c * 8;
        a_dst[p] = su + OFF_A + (uint32_t)(row * A_ROW_B + c * 16);
    }
    const __half* b_src[4]; uint32_t b_dst[4];
#pragma unroll
    for (int p = 0; p < 4; p++) {
        int idx = p * 256 + tid;
        int row = idx >> 5, c = idx & 31;  // 32x16B per 32-row B tile row (256 halves)
        b_src[p] = Bexp + (size_t)row * NTOT + c * 8;
        b_dst[p] = su + OFF_B + (uint32_t)(row * B_ROW_B + c * 16);
    }

    constexpr int NCH = KTOT / BK;

    auto issue_chunk = [&](int cc) {
        int st = cc & 3;
        uint32_t ash = (uint32_t)(st * A_STAGE), bsh = (uint32_t)(st * B_STAGE);
#pragma unroll
        for (int p = 0; p < 2; p++) cp_async16(a_dst[p] + ash, a_src[p] + (size_t)cc * BK);
#pragma unroll
        for (int p = 0; p < 4; p++) cp_async16(b_dst[p] + bsh, b_src[p] + (size_t)cc * BK * NTOT);
    };

    // prologue: stages 0..2
#pragma unroll
    for (int s = 0; s < 3; s++) { issue_chunk(s); cp_commit(); }

    int wm = wid & 1, wn = wid >> 1;        // warp tile 64x64
    int g = lane >> 2, tg = lane & 3;
    uint32_t rowSel = (uint32_t)(lane & 15);
    uint32_t colSel = (uint32_t)((lane >> 4) << 3);

    float acc[4][8][4];
#pragma unroll
    for (int i = 0; i < 4; i++)
#pragma unroll
        for (int j = 0; j < 8; j++)
#pragma unroll
            for (int r = 0; r < 4; r++) acc[i][j][r] = 0.f;

    for (int c = 0; c < NCH; c++) {
        if (c <= NCH - 3) cp_wait<2>();
        else if (c == NCH - 2) cp_wait<1>();
        else cp_wait<0>();
        __syncthreads();
        if (c + 3 < NCH) { issue_chunk(c + 3); cp_commit(); }

        int s = c & 3;
        uint32_t aB = su + OFF_A + (uint32_t)(s * A_STAGE);
        uint32_t bB = su + OFF_B + (uint32_t)(s * B_STAGE);
#pragma unroll
        for (int ks = 0; ks < 2; ks++) {
            uint32_t a[4][4];
#pragma unroll
            for (int mt = 0; mt < 4; mt++) {
                uint32_t addr = aB + (uint32_t)((wm * 64 + mt * 16) + rowSel) * A_ROW_B
                                   + (uint32_t)(ks * 16) * 2 + colSel * 2;
                LDM_X4(a[mt][0], a[mt][1], a[mt][2], a[mt][3], addr);
            }
            uint32_t b[8][2];
#pragma unroll
            for (int np = 0; np < 4; np++) {
                uint32_t addr = bB + (uint32_t)(ks * 16 + rowSel) * B_ROW_B
                                   + (uint32_t)(wn * 64 + np * 16) * 2 + colSel * 2;
                LDM_X4_T(b[2 * np][0], b[2 * np][1], b[2 * np + 1][0], b[2 * np + 1][1], addr);
            }
#pragma unroll
            for (int mt = 0; mt < 4; mt++)
#pragma unroll
                for (int nt = 0; nt < 8; nt++)
                    MMA_F16(acc[mt][nt], a[mt], b[nt]);
        }
    }

    // ---- epilogue ----
#pragma unroll
    for (int mt = 0; mt < 4; mt++) {
        int m_lo = m0 + wm * 64 + mt * 16 + g;
        int m_hi = m_lo + 8;
        bool v_lo = (m_lo < cnt), v_hi = (m_hi < cnt);
        if (MODE == 0) {
            __half* row_lo = g_h + (size_t)(base + (v_lo ? m_lo : 0)) * D_FF;
            __half* row_hi = g_h + (size_t)(base + (v_hi ? m_hi : 0)) * D_FF;
#pragma unroll
            for (int nt = 0; nt < 8; nt++) {
                int col = n0 + wn * 64 + nt * 8 + tg * 2;
                if (v_lo) {
                    __half2 h = __floats2half2_rn(
                        fmaxf(acc[mt][nt][0] + bias_s[col - n0], 0.f),
                        fmaxf(acc[mt][nt][1] + bias_s[col - n0 + 1], 0.f));
                    *(__half2*)(row_lo + col) = h;
                }
                if (v_hi) {
                    __half2 h = __floats2half2_rn(
                        fmaxf(acc[mt][nt][2] + bias_s[col - n0], 0.f),
                        fmaxf(acc[mt][nt][3] + bias_s[col - n0 + 1], 0.f));
                    *(__half2*)(row_hi + col) = h;
                }
            }
        } else {
            float* row_lo = g_y + (size_t)(base + (v_lo ? m_lo : 0)) * D_MODEL;
            float* row_hi = g_y + (size_t)(base + (v_hi ? m_hi : 0)) * D_MODEL;
#pragma unroll
            for (int nt = 0; nt < 8; nt++) {
                int col = n0 + wn * 64 + nt * 8 + tg * 2;
                if (v_lo) {
                    float2 v; v.x = acc[mt][nt][0]; v.y = acc[mt][nt][1];
                    *(float2*)(row_lo + col) = v;
                }
                if (v_hi) {
                    float2 v; v.x = acc[mt][nt][2]; v.y = acc[mt][nt][3];
                    *(float2*)(row_hi + col) = v;
                }
            }
        }
    }
}

// out[t] = w0*(y0 + b2[e0]) + w1*(y1 + b2[e1])
__global__ void k_combine(const float* __restrict__ b2, float* __restrict__ out) {
    int t = blockIdx.x, c = threadIdx.x;   // 256 threads, one float4 each
    uint32_t p0 = g_tk[t * 2], p1 = g_tk[t * 2 + 1];
    float w0 = g_tw[t * 2], w1 = g_tw[t * 2 + 1];
    int e0 = p0 >> 12, s0 = p0 & 4095;
    int e1 = p1 >> 12, s1 = p1 & 4095;
    const float4* y0 = (const float4*)(g_y + (size_t)(g_base[e0] + s0) * D_MODEL);
    const float4* y1 = (const float4*)(g_y + (size_t)(g_base[e1] + s1) * D_MODEL);
    const float4* d0 = (const float4*)(b2 + (size_t)e0 * D_MODEL);
    const float4* d1 = (const float4*)(b2 + (size_t)e1 * D_MODEL);
    float4 A = y0[c], B = y1[c], D0 = d0[c], D1 = d1[c], R;
    R.x = w0 * (A.x + D0.x) + w1 * (B.x + D1.x);
    R.y = w0 * (A.y + D0.y) + w1 * (B.y + D1.y);
    R.z = w0 * (A.z + D0.z) + w1 * (B.z + D1.z);
    R.w = w0 * (A.w + D0.w) + w1 * (B.w + D1.w);
    ((float4*)(out + (size_t)t * D_MODEL))[c] = R;
}

// ---------------- launch ----------------
extern "C" void kernel_launch(void* const* d_in, const int* in_sizes, int n_in,
                              void* d_out, int out_size) {
    const float* x  = (const float*)d_in[0];
    const float* Wg = (const float*)d_in[1];
    const float* W1 = (const float*)d_in[2];
    const float* b1 = (const float*)d_in[3];
    const float* W2 = (const float*)d_in[4];
    const float* b2 = (const float*)d_in[5];
    float* out = (float*)d_out;

    static bool attr_done = false;
    if (!attr_done) {
        cudaFuncSetAttribute(k_mma_gemm<D_MODEL, D_FF, 0>,
                             cudaFuncAttributeMaxDynamicSharedMemorySize, SMEM_BYTES);
        cudaFuncSetAttribute(k_mma_gemm<D_FF, D_MODEL, 1>,
                             cudaFuncAttributeMaxDynamicSharedMemorySize, SMEM_BYTES);
        attr_done = true;
    }

    k_zero_cnt<<<1, 32>>>();
    k_router<<<T_TOK / 8, 256>>>(x, Wg);
    k_scan<<<1, 32>>>();
    k_gather<<<dim3(512, NUM_EXP), 256>>>(x);

    {
        int n4 = NUM_EXP * D_MODEL * D_FF / 4;
        int blocks = (n4 + 255) / 256;
        __half* w1h; cudaGetSymbolAddress((void**)&w1h, g_w1h);
        __half* w2h; cudaGetSymbolAddress((void**)&w2h, g_w2h);
        k_cvt<<<blocks, 256>>>((const float4*)W1, w1h, n4);
        k_cvt<<<blocks, 256>>>((const float4*)W2, w2h, n4);
    }

    // GEMM1: h = relu(xg @ W1 + b1)
    k_mma_gemm<D_MODEL, D_FF, 0>
        <<<dim3(D_FF / BN, T_TOK / BM, NUM_EXP), 256, SMEM_BYTES>>>(b1);
    // GEMM2: y = h @ W2
    k_mma_gemm<D_FF, D_MODEL, 1>
        <<<dim3(D_MODEL / BN, T_TOK / BM, NUM_EXP), 256, SMEM_BYTES>>>(b2);
    // combine
    k_combine<<<T_TOK, 256>>>(b2, out);
}